// round 1
// baseline (speedup 1.0000x reference)
#include <cuda_runtime.h>
#include <cstddef>

// Problem constants (fixed shapes from reference)
#define BB 16384
#define GG 128
#define SS 64
#define HH 10
#define PHH 100

// 8MB scratch for gene_layer, stored TRANSPOSED: glT[g][b]
__device__ float g_glT[GG * BB];

// ---------------------------------------------------------------------------
// packed fp32x2 FMA (Blackwell sm_100+; only reachable via inline PTX)
// ---------------------------------------------------------------------------
__device__ __forceinline__ unsigned long long f2fma(unsigned long long a,
                                                    unsigned long long b,
                                                    unsigned long long c) {
    unsigned long long d;
    asm("fma.rn.f32x2 %0, %1, %2, %3;" : "=l"(d) : "l"(a), "l"(b), "l"(c));
    return d;
}
__device__ __forceinline__ float f2lo(unsigned long long a) {
    return __uint_as_float((unsigned)a);
}
__device__ __forceinline__ float f2hi(unsigned long long a) {
    return __uint_as_float((unsigned)(a >> 32));
}

extern __shared__ unsigned char dynsmem[];

// ---------------------------------------------------------------------------
// Kernel A: per-gene MLP  gene_layer[b,g] = W2 . relu(x[b,g,:] @ W1[g] + b1) + b2
// Grid: (B/256, G). 128 threads. Each thread computes 2 rows x all 10 h.
// ---------------------------------------------------------------------------
#define A_ROWS 256
#define A_THREADS 128
#define XSTR (A_ROWS + 1)   // row-dim stride in ulonglong2 units (pad vs banks)

// dyn smem: xq[16][XSTR] ulonglong2 | wq[10][16] ulonglong2 | sb1[16] sW2[16] sb2[4]
#define A_SMEM_BYTES (16 * XSTR * 16 + 10 * 16 * 16 + (16 + 16 + 4) * 4)

__global__ void __launch_bounds__(A_THREADS)
kernelA(const float* __restrict__ x, const float* __restrict__ W1,
        const float* __restrict__ b1, const float* __restrict__ W2,
        const float* __restrict__ b2) {
    ulonglong2* xq = (ulonglong2*)dynsmem;                 // [16][XSTR]
    ulonglong2* wq = xq + 16 * XSTR;                       // [10][16]
    float* ftail = (float*)(wq + 10 * 16);
    float* sb1 = ftail;        // [16]
    float* sW2 = ftail + 16;   // [16]
    float* sb2 = ftail + 32;   // [1]

    const int tid = threadIdx.x;
    const int g = blockIdx.y;
    const int b0 = blockIdx.x * A_ROWS;

    // --- stage W1[g] packed: wq[h][q] = 4 floats {W1[4q..4q+3][h]} ---
    {
        const float* W1g = W1 + g * (SS * HH);
        float* wqf = (float*)wq;
        for (int i = tid; i < SS * HH; i += A_THREADS) {
            int s = i / HH, h = i - s * HH;
            wqf[(h * 16 + (s >> 2)) * 4 + (s & 3)] = W1g[i];
        }
        if (tid < HH) {
            sb1[tid] = b1[g * HH + tid];
            sW2[tid] = W2[g * HH + tid];
        }
        if (tid == 0) sb2[0] = b2[g];
    }

    // --- stage x tile transposed: xq[q][r] = x[b0+r, g, 4q..4q+3] ---
    // warp instruction covers one contiguous 256B row -> fully coalesced
    for (int i = tid; i < A_ROWS * 16; i += A_THREADS) {
        int q = i & 15, r = i >> 4;
        const ulonglong2* src =
            (const ulonglong2*)(x + (((size_t)(b0 + r)) * GG + g) * SS);
        xq[q * XSTR + r] = src[q];
    }
    __syncthreads();

    // --- compute: 2 rows per thread, 10 h, f32x2 over s-pairs ---
    unsigned long long a0[HH], a1[HH];
#pragma unroll
    for (int h = 0; h < HH; h++) { a0[h] = 0ull; a1[h] = 0ull; }

    const int r0 = tid;
    const int r1 = tid + A_THREADS;
#pragma unroll
    for (int q = 0; q < 16; q++) {
        ulonglong2 xa = xq[q * XSTR + r0];   // conflict-free: lanes = rows
        ulonglong2 xb = xq[q * XSTR + r1];
#pragma unroll
        for (int h = 0; h < HH; h++) {
            ulonglong2 w = wq[h * 16 + q];   // broadcast
            a0[h] = f2fma(xa.x, w.x, a0[h]);
            a0[h] = f2fma(xa.y, w.y, a0[h]);
            a1[h] = f2fma(xb.x, w.x, a1[h]);
            a1[h] = f2fma(xb.y, w.y, a1[h]);
        }
    }

    // --- epilogue: relu + H->1 projection, coalesced store to glT ---
    float o0 = sb2[0], o1 = sb2[0];
#pragma unroll
    for (int h = 0; h < HH; h++) {
        float v0 = f2lo(a0[h]) + f2hi(a0[h]) + sb1[h];
        float v1 = f2lo(a1[h]) + f2hi(a1[h]) + sb1[h];
        v0 = fmaxf(v0, 0.f);
        v1 = fmaxf(v1, 0.f);
        o0 = fmaf(v0, sW2[h], o0);
        o1 = fmaf(v1, sW2[h], o1);
    }
    float* glrow = g_glT + (size_t)g * BB + b0;
    glrow[r0] = o0;
    glrow[r1] = o1;
}

// ---------------------------------------------------------------------------
// Kernel B: out[b] = relu(gl[b,:] @ Wp1 + bp1) @ Wp2 + bp2
// Grid: B/64 = 256 blocks, 128 threads = 32 row-slots (2 rows each) x 4 j-quarters
// ---------------------------------------------------------------------------
#define B_THREADS 128
#define B_ROWS 64
#define B_SMEM_FLOATS (GG * B_ROWS + GG * PHH + 104 + 104 + 4 * B_ROWS)
#define B_SMEM_BYTES (B_SMEM_FLOATS * 4)

__global__ void __launch_bounds__(B_THREADS)
kernelB(const float* __restrict__ Wp1, const float* __restrict__ bp1,
        const float* __restrict__ Wp2, const float* __restrict__ bp2,
        float* __restrict__ out) {
    float* gls = (float*)dynsmem;             // [G][64] rows of this tile (g-major)
    float* sWp1 = gls + GG * B_ROWS;          // [G][100]
    float* sbp1 = sWp1 + GG * PHH;            // [100] (padded 104)
    float* sWp2 = sbp1 + 104;                 // [100] (padded 104)
    float* op = sWp2 + 104;                   // [4][64] partial outputs

    const int tid = threadIdx.x;
    const int b0 = blockIdx.x * B_ROWS;

    // stage gene_layer tile from transposed scratch (coalesced: rows contiguous)
    for (int i = tid; i < GG * B_ROWS; i += B_THREADS) {
        int r = i & (B_ROWS - 1), g = i >> 6;
        gls[g * B_ROWS + r] = g_glT[(size_t)g * BB + b0 + r];
    }
    for (int i = tid; i < GG * PHH; i += B_THREADS) sWp1[i] = Wp1[i];
    if (tid < PHH) {
        sbp1[tid] = bp1[tid];
        sWp2[tid] = Wp2[tid];
    }
    __syncthreads();

    const int rowslot = tid & 31;   // 2 adjacent rows per thread
    const int jsub = tid >> 5;      // j quarter: [25*jsub, 25*jsub+25)
    const int jb = jsub * 25;

    float acc0[25], acc1[25];
#pragma unroll
    for (int c = 0; c < 25; c++) { acc0[c] = 0.f; acc1[c] = 0.f; }

#pragma unroll 2
    for (int g = 0; g < GG; g++) {
        float2 xv = ((const float2*)(gls + g * B_ROWS))[rowslot];  // conflict-free
        const float* wrow = sWp1 + g * PHH + jb;                   // broadcast
#pragma unroll
        for (int c = 0; c < 25; c++) {
            float w = wrow[c];
            acc0[c] = fmaf(xv.x, w, acc0[c]);
            acc1[c] = fmaf(xv.y, w, acc1[c]);
        }
    }

    float o0 = 0.f, o1 = 0.f;
#pragma unroll
    for (int c = 0; c < 25; c++) {
        float p0 = fmaxf(acc0[c] + sbp1[jb + c], 0.f);
        float p1 = fmaxf(acc1[c] + sbp1[jb + c], 0.f);
        o0 = fmaf(p0, sWp2[jb + c], o0);
        o1 = fmaf(p1, sWp2[jb + c], o1);
    }
    op[jsub * B_ROWS + 2 * rowslot] = o0;
    op[jsub * B_ROWS + 2 * rowslot + 1] = o1;
    __syncthreads();

    if (tid < B_ROWS) {
        float v = op[tid] + op[B_ROWS + tid] + op[2 * B_ROWS + tid] +
                  op[3 * B_ROWS + tid] + bp2[0];
        out[b0 + tid] = v;
    }
}

// ---------------------------------------------------------------------------
extern "C" void kernel_launch(void* const* d_in, const int* in_sizes, int n_in,
                              void* d_out, int out_size) {
    const float* x   = (const float*)d_in[0];
    const float* W1  = (const float*)d_in[1];
    const float* b1  = (const float*)d_in[2];
    const float* W2  = (const float*)d_in[3];
    const float* b2  = (const float*)d_in[4];
    const float* Wp1 = (const float*)d_in[5];
    const float* bp1 = (const float*)d_in[6];
    const float* Wp2 = (const float*)d_in[7];
    const float* bp2 = (const float*)d_in[8];
    float* out = (float*)d_out;

    // idempotent, called every launch (no static guards allowed)
    cudaFuncSetAttribute(kernelA, cudaFuncAttributeMaxDynamicSharedMemorySize,
                         A_SMEM_BYTES);
    cudaFuncSetAttribute(kernelB, cudaFuncAttributeMaxDynamicSharedMemorySize,
                         B_SMEM_BYTES);

    dim3 gridA(BB / A_ROWS, GG);
    kernelA<<<gridA, A_THREADS, A_SMEM_BYTES>>>(x, W1, b1, W2, b2);

    dim3 gridB(BB / B_ROWS);
    kernelB<<<gridB, B_THREADS, B_SMEM_BYTES>>>(Wp1, bp1, Wp2, bp2, out);
}